// round 7
// baseline (speedup 1.0000x reference)
#include <cuda_runtime.h>
#include <cuda_fp16.h>
#include <cuda_bf16.h>
#include <cstdint>

#define S1 4097
#define SMAX 4096
#define DM 160
#define NH 4
#define HD 40
#define BATCH 4
#define KT 64
#define NTK 65           // ceil(4097/64)
#define L2E 1.4426950408889634f
#define KP_TILE 2560     // floats per K fragment tile (5kt*4j*32lane*4)
#define VP_TILE 1536     // u32 per V fragment tile   (4kt*3j*32lane*4)

// ---------------- device scratch ----------------
__device__ float g_f[BATCH * S1 * DM];
__device__ float g_q[BATCH * NH * S1 * HD];
__device__ float g_k[BATCH * NH * S1 * HD];
__device__ float g_v[BATCH * NH * S1 * HD];
__device__ float g_att[BATCH * NH * S1 * HD];
__device__ float g_stats[BATCH * SMAX * 2];
__device__ float    g_kp[BATCH * NH * NTK * KP_TILE];   // K in mma B-frag order (tf32)
__device__ uint32_t g_vp[BATCH * NH * NTK * VP_TILE];   // V in mma B-frag order (f16x2)

// ---------------- helpers ----------------
__device__ __forceinline__ void mma_tf32(float* c, const uint32_t* a, const uint32_t* b) {
    asm volatile(
        "mma.sync.aligned.m16n8k8.row.col.f32.tf32.tf32.f32 "
        "{%0,%1,%2,%3}, {%4,%5,%6,%7}, {%8,%9}, {%0,%1,%2,%3};"
        : "+f"(c[0]), "+f"(c[1]), "+f"(c[2]), "+f"(c[3])
        : "r"(a[0]), "r"(a[1]), "r"(a[2]), "r"(a[3]), "r"(b[0]), "r"(b[1]));
}
__device__ __forceinline__ void mma_f16(float* c, const uint32_t* a, const uint32_t* b) {
    asm volatile(
        "mma.sync.aligned.m16n8k16.row.col.f32.f16.f16.f32 "
        "{%0,%1,%2,%3}, {%4,%5,%6,%7}, {%8,%9}, {%0,%1,%2,%3};"
        : "+f"(c[0]), "+f"(c[1]), "+f"(c[2]), "+f"(c[3])
        : "r"(a[0]), "r"(a[1]), "r"(a[2]), "r"(a[3]), "r"(b[0]), "r"(b[1]));
}
__device__ __forceinline__ float to_tf32(float x) {
    float r;
    asm("cvt.rna.tf32.f32 %0, %1;" : "=f"(r) : "f"(x));
    return r;
}
__device__ __forceinline__ uint32_t pack_ex2_f16x2(float lo, float hi) {
    uint32_t p, r;
    asm("cvt.rn.f16x2.f32 %0, %1, %2;" : "=r"(p) : "f"(hi), "f"(lo));
    asm("ex2.approx.f16x2 %0, %1;" : "=r"(r) : "r"(p));
    return r;
}
__device__ __forceinline__ uint32_t pack_f16x2(float lo, float hi) {
    uint32_t p;
    asm("cvt.rn.f16x2.f32 %0, %1, %2;" : "=r"(p) : "f"(hi), "f"(lo));
    return p;
}
__device__ __forceinline__ uint32_t smem_u32(const void* p) {
    uint32_t a;
    asm("{ .reg .u64 t; cvta.to.shared.u64 t, %1; cvt.u32.u64 %0, t; }" : "=r"(a) : "l"(p));
    return a;
}
#define CP_ASYNC16(sdst, gsrc) \
    asm volatile("cp.async.cg.shared.global [%0], [%1], 16;" :: "r"(sdst), "l"(gsrc))
#define CP_COMMIT() asm volatile("cp.async.commit_group;")
#define CP_WAIT0()  asm volatile("cp.async.wait_group 0;")

// ================= prep: K/V -> fragment-order scratch =================
// grid (NTK, 16), 128 threads. Tile = 64 keys.
__global__ void __launch_bounds__(128) k_prep()
{
    int t = blockIdx.x, bh = blockIdx.y;
    int tid = threadIdx.x, lane = tid & 31, w = tid >> 5;
    int g = lane >> 2, tg = lane & 3;
    const float* kb = g_k + (size_t)bh * S1 * HD;
    const float* vb = g_v + (size_t)bh * S1 * HD;
    float*    kp = g_kp + ((size_t)bh * NTK + t) * KP_TILE;
    uint32_t* vp = g_vp + ((size_t)bh * NTK + t) * VP_TILE;

    for (int c = w; c < 32; c += 4) {
        if (c < 20) {                       // K combos: kt 0..4, j 0..3
            int kt = c >> 2, j = c & 3;
            float4 val;
            float* vv = (float*)&val;
            #pragma unroll
            for (int e = 0; e < 4; e++) {
                int idx = j * 4 + e, nt = idx >> 1, reg = idx & 1;
                int key = t * KT + g + 8 * nt;
                int col = tg + 4 * reg + 8 * kt;
                vv[e] = (key < S1) ? to_tf32(kb[(size_t)key * HD + col]) : 0.f;
            }
            ((float4*)kp)[(kt * 4 + j) * 32 + lane] = val;
        } else {                            // V combos: kt 0..3, j 0..2
            int cc = c - 20, kt = cc / 3, j = cc % 3;
            uint4 val;
            uint32_t* vv = (uint32_t*)&val;
            #pragma unroll
            for (int e = 0; e < 4; e++) {
                int idx = j * 4 + e, nt = idx >> 1, reg = idx & 1;
                int p = 8 * kt + tg + 4 * reg;   // key-pair index
                int d = g + 8 * nt;              // output dim (40=ones col)
                uint32_t r;
                if (d == 40) r = 0x3C003C00u;
                else if (d > 40) r = 0u;
                else {
                    int k0 = t * KT + 2 * p;
                    float v0 = (k0     < S1) ? vb[(size_t)k0 * HD + d]       : 0.f;
                    float v1 = (k0 + 1 < S1) ? vb[(size_t)(k0 + 1) * HD + d] : 0.f;
                    r = pack_f16x2(v0, v1);
                }
                vv[e] = r;
            }
            ((uint4*)vp)[(kt * 3 + j) * 32 + lane] = val;
        }
    }
}

// ================= flash attention v3: cp.async double-buffer + frag smem ====
__global__ void __launch_bounds__(128) k_flash3()
{
    __shared__ uint4 buf[2][1024];          // per tile: K 640 uint4 | V 384 uint4

    const int tid = threadIdx.x, w = tid >> 5, lane = tid & 31;
    const int g = lane >> 2, tg = lane & 3;
    const int qt = blockIdx.x, bh = blockIdx.y;

    const float*    qb = g_q  + (size_t)bh * S1 * HD;
    const float*    kp = g_kp + (size_t)bh * NTK * KP_TILE;
    const uint32_t* vp = g_vp + (size_t)bh * NTK * VP_TILE;

    // ---- Q fragments in registers (loop-invariant) ----
    uint32_t qa[2][5][4];
    #pragma unroll
    for (int mt = 0; mt < 2; mt++) {
        int r0 = qt * 128 + w * 32 + mt * 16 + g;
        #pragma unroll
        for (int kt = 0; kt < 5; kt++) {
            qa[mt][kt][0] = __float_as_uint(to_tf32(qb[(size_t)r0 * HD + tg + 8 * kt] * 0.158113883f));
            qa[mt][kt][1] = __float_as_uint(to_tf32(qb[(size_t)(r0 + 8) * HD + tg + 8 * kt] * 0.158113883f));
            qa[mt][kt][2] = __float_as_uint(to_tf32(qb[(size_t)r0 * HD + tg + 4 + 8 * kt] * 0.158113883f));
            qa[mt][kt][3] = __float_as_uint(to_tf32(qb[(size_t)(r0 + 8) * HD + tg + 4 + 8 * kt] * 0.158113883f));
        }
    }

    float o[2][6][4];
    #pragma unroll
    for (int a = 0; a < 2; a++)
        #pragma unroll
        for (int b = 0; b < 6; b++)
            #pragma unroll
            for (int c = 0; c < 4; c++) o[a][b][c] = 0.f;
    float m[4] = { -1e30f, -1e30f, -1e30f, -1e30f };

    const uint32_t sb0 = smem_u32(&buf[0][0]);
    const uint32_t sb1 = smem_u32(&buf[1][0]);

    // prefetch tile 0
    {
        const char* kg = (const char*)(kp);
        const char* vg = (const char*)(vp);
        #pragma unroll
        for (int i = 0; i < 5; i++)
            CP_ASYNC16(sb0 + (tid + i * 128) * 16, kg + (size_t)(tid + i * 128) * 16);
        #pragma unroll
        for (int i = 0; i < 3; i++)
            CP_ASYNC16(sb0 + 10240 + (tid + i * 128) * 16, vg + (size_t)(tid + i * 128) * 16);
        CP_COMMIT();
    }

    for (int t = 0; t < NTK; t++) {
        CP_WAIT0();
        __syncthreads();            // tile t visible AND everyone finished tile t-1

        if (t + 1 < NTK) {          // prefetch t+1 into the other buffer
            uint32_t sd = ((t + 1) & 1) ? sb1 : sb0;
            const char* kg = (const char*)(kp + (size_t)(t + 1) * KP_TILE);
            const char* vg = (const char*)(vp + (size_t)(t + 1) * VP_TILE);
            #pragma unroll
            for (int i = 0; i < 5; i++)
                CP_ASYNC16(sd + (tid + i * 128) * 16, kg + (size_t)(tid + i * 128) * 16);
            #pragma unroll
            for (int i = 0; i < 3; i++)
                CP_ASYNC16(sd + 10240 + (tid + i * 128) * 16, vg + (size_t)(tid + i * 128) * 16);
            CP_COMMIT();
        }

        const float4* K4 = (const float4*)((t & 1) ? &buf[1][0] : &buf[0][0]);
        const uint4*  V4 = (const uint4*)(((t & 1) ? &buf[1][0] : &buf[0][0]) + 640);

        // ---- S = Q K^T ----
        float s[2][8][4];
        #pragma unroll
        for (int a = 0; a < 2; a++)
            #pragma unroll
            for (int b = 0; b < 8; b++)
                #pragma unroll
                for (int c = 0; c < 4; c++) s[a][b][c] = 0.f;

        #pragma unroll
        for (int kt = 0; kt < 5; kt++) {
            float4 f0 = K4[(kt * 4 + 0) * 32 + lane];
            float4 f1 = K4[(kt * 4 + 1) * 32 + lane];
            float4 f2 = K4[(kt * 4 + 2) * 32 + lane];
            float4 f3 = K4[(kt * 4 + 3) * 32 + lane];
            uint32_t bb[8][2];
            bb[0][0] = __float_as_uint(f0.x); bb[0][1] = __float_as_uint(f0.y);
            bb[1][0] = __float_as_uint(f0.z); bb[1][1] = __float_as_uint(f0.w);
            bb[2][0] = __float_as_uint(f1.x); bb[2][1] = __float_as_uint(f1.y);
            bb[3][0] = __float_as_uint(f1.z); bb[3][1] = __float_as_uint(f1.w);
            bb[4][0] = __float_as_uint(f2.x); bb[4][1] = __float_as_uint(f2.y);
            bb[5][0] = __float_as_uint(f2.z); bb[5][1] = __float_as_uint(f2.w);
            bb[6][0] = __float_as_uint(f3.x); bb[6][1] = __float_as_uint(f3.y);
            bb[7][0] = __float_as_uint(f3.z); bb[7][1] = __float_as_uint(f3.w);
            #pragma unroll
            for (int mt = 0; mt < 2; mt++)
                #pragma unroll
                for (int nt = 0; nt < 8; nt++) mma_tf32(s[mt][nt], qa[mt][kt], bb[nt]);
        }

        // ---- mask invalid keys (last tile only) ----
        if (t == NTK - 1) {
            #pragma unroll
            for (int nt = 0; nt < 8; nt++) {
                int base = t * KT + 8 * nt + 2 * tg;
                if (base >= S1) {
                    s[0][nt][0] = s[0][nt][2] = s[1][nt][0] = s[1][nt][2] = -1e30f;
                }
                if (base + 1 >= S1) {
                    s[0][nt][1] = s[0][nt][3] = s[1][nt][1] = s[1][nt][3] = -1e30f;
                }
            }
        }

        // ---- online softmax ----
        float corr[4], mL[4];
        #pragma unroll
        for (int r = 0; r < 4; r++) {
            int mt = r >> 1, hf = r & 1;
            float mx = -1e30f;
            #pragma unroll
            for (int nt = 0; nt < 8; nt++) {
                mx = fmaxf(mx, s[mt][nt][2 * hf]);
                mx = fmaxf(mx, s[mt][nt][2 * hf + 1]);
            }
            mx = fmaxf(mx, __shfl_xor_sync(0xFFFFFFFFu, mx, 1));
            mx = fmaxf(mx, __shfl_xor_sync(0xFFFFFFFFu, mx, 2));
            float mn = fmaxf(m[r], mx);
            corr[r] = __expf(m[r] - mn);
            m[r] = mn;
            mL[r] = mn * L2E;
        }

        #pragma unroll
        for (int mt = 0; mt < 2; mt++)
            #pragma unroll
            for (int nt = 0; nt < 6; nt++) {
                o[mt][nt][0] *= corr[mt * 2];
                o[mt][nt][1] *= corr[mt * 2];
                o[mt][nt][2] *= corr[mt * 2 + 1];
                o[mt][nt][3] *= corr[mt * 2 + 1];
            }

        uint32_t pf[2][8][2];
        #pragma unroll
        for (int mt = 0; mt < 2; mt++)
            #pragma unroll
            for (int nt = 0; nt < 8; nt++) {
                float f0 = __fmaf_rn(s[mt][nt][0], L2E, -mL[mt * 2]);
                float f1 = __fmaf_rn(s[mt][nt][1], L2E, -mL[mt * 2]);
                float f2 = __fmaf_rn(s[mt][nt][2], L2E, -mL[mt * 2 + 1]);
                float f3 = __fmaf_rn(s[mt][nt][3], L2E, -mL[mt * 2 + 1]);
                pf[mt][nt][0] = pack_ex2_f16x2(f0, f1);
                pf[mt][nt][1] = pack_ex2_f16x2(f2, f3);
            }

        // ---- O += P V ----
        #pragma unroll
        for (int kt = 0; kt < 4; kt++) {
            uint4 b0 = V4[(kt * 3 + 0) * 32 + lane];
            uint4 b1 = V4[(kt * 3 + 1) * 32 + lane];
            uint4 b2 = V4[(kt * 3 + 2) * 32 + lane];
            uint32_t bb[6][2];
            bb[0][0] = b0.x; bb[0][1] = b0.y;
            bb[1][0] = b0.z; bb[1][1] = b0.w;
            bb[2][0] = b1.x; bb[2][1] = b1.y;
            bb[3][0] = b1.z; bb[3][1] = b1.w;
            bb[4][0] = b2.x; bb[4][1] = b2.y;
            bb[5][0] = b2.z; bb[5][1] = b2.w;
            #pragma unroll
            for (int mt = 0; mt < 2; mt++) {
                uint32_t aa[4] = { pf[mt][2 * kt][0], pf[mt][2 * kt][1],
                                   pf[mt][2 * kt + 1][0], pf[mt][2 * kt + 1][1] };
                #pragma unroll
                for (int nt = 0; nt < 6; nt++) mma_f16(o[mt][nt], aa, bb[nt]);
            }
        }
    }

    // ---- epilogue ----
    #pragma unroll
    for (int mt = 0; mt < 2; mt++) {
        float l0 = __shfl_sync(0xFFFFFFFFu, o[mt][5][0], lane & ~3);
        float l1 = __shfl_sync(0xFFFFFFFFu, o[mt][5][2], lane & ~3);
        float inv0 = 1.f / l0, inv1 = 1.f / l1;
        int row0 = qt * 128 + w * 32 + mt * 16 + g;
        float* ob0 = g_att + ((size_t)bh * S1 + row0) * HD;
        float* ob1 = g_att + ((size_t)bh * S1 + row0 + 8) * HD;
        #pragma unroll
        for (int nt = 0; nt < 5; nt++) {
            int d = 8 * nt + 2 * tg;
            *(float2*)(ob0 + d) = make_float2(o[mt][nt][0] * inv0, o[mt][nt][1] * inv0);
            *(float2*)(ob1 + d) = make_float2(o[mt][nt][2] * inv1, o[mt][nt][3] * inv1);
        }
    }
}

// ================= conv =================
__global__ void k_conv(const float* __restrict__ x,
                       const float* __restrict__ w1, const float* __restrict__ b1,
                       const float* __restrict__ w2, const float* __restrict__ b2,
                       const float* __restrict__ pe)
{
    int j = blockIdx.x, i = blockIdx.y, b = blockIdx.z;
    int tid = threadIdx.x;
    __shared__ __align__(16) float patch[256];
    __shared__ __align__(16) float out1[64];
    for (int t = tid; t < 256; t += 160) {
        int c0 = t >> 2, k = t & 3, ky = k >> 1, kx = k & 1;
        patch[t] = x[((b * 64 + c0) * 128 + (2 * i + ky)) * 128 + (2 * j + kx)];
    }
    __syncthreads();
    if (tid < 64) {
        const float4* p4 = (const float4*)patch;
        const float4* w4 = (const float4*)(w1 + tid * 256);
        float4 a = make_float4(0.f, 0.f, 0.f, 0.f);
        #pragma unroll
        for (int c0 = 0; c0 < 64; c0++) {
            float4 pv = p4[c0], wv = w4[c0];
            a.x += pv.x * wv.x; a.y += pv.y * wv.y;
            a.z += pv.z * wv.z; a.w += pv.w * wv.w;
        }
        out1[tid] = b1[tid] + a.x + a.y + a.z + a.w;
    }
    __syncthreads();
    const float4* o4 = (const float4*)out1;
    const float4* w24 = (const float4*)(w2 + tid * 64);
    float4 a = make_float4(0.f, 0.f, 0.f, 0.f);
    #pragma unroll
    for (int c1 = 0; c1 < 16; c1++) {
        float4 ov = o4[c1], wv = w24[c1];
        a.x += ov.x * wv.x; a.y += ov.y * wv.y;
        a.z += ov.z * wv.z; a.w += ov.w * wv.w;
    }
    float acc = b2[tid] + a.x + a.y + a.z + a.w;
    acc = (acc >= 0.f) ? acc : 0.01f * acc;
    int s = i * 64 + j;
    g_f[((size_t)b * S1 + s) * DM + tid] = acc + pe[s];
}

__global__ void k_pad(const float* __restrict__ pe)
{
    int t = blockIdx.x * blockDim.x + threadIdx.x;
    if (t < BATCH * DM) {
        int b = t / DM, c = t % DM;
        g_f[((size_t)b * S1 + SMAX) * DM + c] = pe[SMAX];
    }
}

// ================= QKV projection (smem-tiled GEMM) =================
__global__ void __launch_bounds__(512) k_qkv(const float* __restrict__ wq,
                                             const float* __restrict__ wk,
                                             const float* __restrict__ wv)
{
    __shared__ float fsT[160 * 33];
    __shared__ float wsT[40 * 161];
    const int NROWS = BATCH * S1;
    int row0 = blockIdx.x * 32;
    const float* w = (blockIdx.y == 0) ? wq : ((blockIdx.y == 1) ? wk : wv);
    float* outp = (blockIdx.y == 0) ? g_q : ((blockIdx.y == 1) ? g_k : g_v);
    int tid = threadIdx.x;

    for (int idx = tid; idx < 32 * DM; idx += 512) {
        int mm = idx / DM, c = idx % DM;
        int gr = row0 + mm;
        fsT[c * 33 + mm] = (gr < NROWS) ? g_f[(size_t)gr * DM + c] : 0.f;
    }

    int tn = tid & 31;
    int tm = tid >> 5;
    int n0 = tn * 5;
    int m0 = tm * 2;
    float acc[2][5] = {};

    for (int c4 = 0; c4 < 4; c4++) {
        __syncthreads();
        for (int idx = tid; idx < DM * 40; idx += 512) {
            int n = idx / 40, kk = idx % 40;
            wsT[kk * 161 + n] = w[n * DM + c4 * 40 + kk];
        }
        __syncthreads();
        #pragma unroll 4
        for (int kk = 0; kk < 40; kk++) {
            int k = c4 * 40 + kk;
            float f0 = fsT[k * 33 + m0];
            float f1 = fsT[k * 33 + m0 + 1];
            #pragma unroll
            for (int i = 0; i < 5; i++) {
                float wv_ = wsT[kk * 161 + n0 + i];
                acc[0][i] = __fmaf_rn(f0, wv_, acc[0][i]);
                acc[1][i] = __fmaf_rn(f1, wv_, acc[1][i]);
            }
        }
    }

    #pragma unroll
    for (int mi = 0; mi < 2; mi++) {
        int gr = row0 + m0 + mi;
        if (gr >= NROWS) continue;
        int b = gr / S1, s = gr % S1;
        #pragma unroll
        for (int i = 0; i < 5; i++) {
            int n = n0 + i;
            int h = n / HD, d = n % HD;
            outp[(((size_t)b * NH + h) * S1 + s) * HD + d] = acc[mi][i];
        }
    }
}

// ================= LN stats =================
__global__ void k_stats()
{
    int r = blockIdx.x;
    int b = r >> 12, s = r & 4095;
    int tid = threadIdx.x;
    float v = 0.f;
    if (tid < DM) {
        int h = tid / HD, d = tid % HD;
        v = g_att[(((size_t)b * NH + h) * S1 + s) * HD + d];
    }
    __shared__ float r1[256], r2[256];
    r1[tid] = v; r2[tid] = v * v;
    __syncthreads();
    for (int off = 128; off > 0; off >>= 1) {
        if (tid < off) { r1[tid] += r1[tid + off]; r2[tid] += r2[tid + off]; }
        __syncthreads();
    }
    if (tid == 0) {
        float mean = r1[0] * (1.f / DM);
        float var  = r2[0] * (1.f / DM) - mean * mean;
        g_stats[2 * r]     = mean;
        g_stats[2 * r + 1] = rsqrtf(var + 1e-5f);
    }
}

// ================= LN + residual + upsample =================
__global__ void k_out(const float* __restrict__ ln_w, const float* __restrict__ ln_b,
                      float* __restrict__ out)
{
    int tx = threadIdx.x, ty = threadIdx.y;
    int j = blockIdx.x * 32 + tx;
    int i = blockIdx.y;
    int bz = blockIdx.z;
    int b = bz / 20, cg = bz % 20;
    int c = cg * 8 + ty;
    int s = i * 64 + j;
    int h = c / HD, d = c % HD;
    float v = g_att[(((size_t)b * NH + h) * S1 + s) * HD + d];
    float mean = g_stats[2 * (b * SMAX + s)];
    float rstd = g_stats[2 * (b * SMAX + s) + 1];
    float ln = (v - mean) * rstd * ln_w[c] + ln_b[c];
    float ov = ln + v;
    size_t base = (((size_t)b * DM + c) * 128 + 2 * i) * 128 + 2 * j;
    float2 v2 = make_float2(ov, ov);
    *(float2*)(out + base)       = v2;
    *(float2*)(out + base + 128) = v2;
}

// ---------------- launch ----------------
extern "C" void kernel_launch(void* const* d_in, const int* in_sizes, int n_in,
                              void* d_out, int out_size)
{
    const float* x   = (const float*)d_in[0];
    const float* w1  = (const float*)d_in[1];
    const float* b1  = (const float*)d_in[2];
    const float* w2  = (const float*)d_in[3];
    const float* b2  = (const float*)d_in[4];
    const float* pe  = (const float*)d_in[5];
    const float* wq  = (const float*)d_in[6];
    const float* wk  = (const float*)d_in[7];
    const float* wv  = (const float*)d_in[8];
    const float* lnw = (const float*)d_in[9];
    const float* lnb = (const float*)d_in[10];
    float* out = (float*)d_out;

    k_conv<<<dim3(64, 64, BATCH), 160>>>(x, w1, b1, w2, b2, pe);
    k_pad<<<1, BATCH * DM>>>(pe);
    k_qkv<<<dim3((BATCH * S1 + 31) / 32, 3), 512>>>(wq, wk, wv);
    k_prep<<<dim3(NTK, BATCH * NH), 128>>>();
    k_flash3<<<dim3(SMAX / 128, BATCH * NH), 128>>>();
    k_stats<<<BATCH * SMAX, 256>>>();
    k_out<<<dim3(2, 64, BATCH * 20), dim3(32, 8)>>>(lnw, lnb, out);
}

// round 8
// speedup vs baseline: 1.7795x; 1.7795x over previous
#include <cuda_runtime.h>
#include <cuda_fp16.h>
#include <cuda_bf16.h>
#include <cstdint>

#define S1 4097
#define SMAX 4096
#define DM 160
#define NH 4
#define HD 40
#define BATCH 4
#define KT 64
#define NTK 65           // ceil(4097/64)
#define L2E 1.4426950408889634f
#define KP_TILE 2560     // floats per K fragment tile (5kt*4j*32lane*4)
#define VP_TILE 1536     // u32 per V fragment tile   (4kt*3j*32lane*4)

// ---------------- device scratch ----------------
__device__ float g_f[BATCH * S1 * DM];
__device__ float g_q[BATCH * NH * S1 * HD];
__device__ float g_k[BATCH * NH * S1 * HD];
__device__ float g_v[BATCH * NH * S1 * HD];
__device__ float g_att[BATCH * NH * S1 * HD];
__device__ float g_stats[BATCH * SMAX * 2];
__device__ float    g_kp[BATCH * NH * NTK * KP_TILE];   // K in mma B-frag order (tf32)
__device__ uint32_t g_vp[BATCH * NH * NTK * VP_TILE];   // V in mma B-frag order (f16x2)

// ---------------- helpers ----------------
__device__ __forceinline__ void mma_tf32(float* c, const uint32_t* a, const uint32_t* b) {
    asm volatile(
        "mma.sync.aligned.m16n8k8.row.col.f32.tf32.tf32.f32 "
        "{%0,%1,%2,%3}, {%4,%5,%6,%7}, {%8,%9}, {%0,%1,%2,%3};"
        : "+f"(c[0]), "+f"(c[1]), "+f"(c[2]), "+f"(c[3])
        : "r"(a[0]), "r"(a[1]), "r"(a[2]), "r"(a[3]), "r"(b[0]), "r"(b[1]));
}
__device__ __forceinline__ void mma_f16(float* c, const uint32_t* a, const uint32_t* b) {
    asm volatile(
        "mma.sync.aligned.m16n8k16.row.col.f32.f16.f16.f32 "
        "{%0,%1,%2,%3}, {%4,%5,%6,%7}, {%8,%9}, {%0,%1,%2,%3};"
        : "+f"(c[0]), "+f"(c[1]), "+f"(c[2]), "+f"(c[3])
        : "r"(a[0]), "r"(a[1]), "r"(a[2]), "r"(a[3]), "r"(b[0]), "r"(b[1]));
}
__device__ __forceinline__ float to_tf32(float x) {
    float r;
    asm("cvt.rna.tf32.f32 %0, %1;" : "=f"(r) : "f"(x));
    return r;
}
__device__ __forceinline__ uint32_t pack_ex2_f16x2(float lo, float hi) {
    uint32_t p, r;
    asm("cvt.rn.f16x2.f32 %0, %1, %2;" : "=r"(p) : "f"(hi), "f"(lo));
    asm("ex2.approx.f16x2 %0, %1;" : "=r"(r) : "r"(p));
    return r;
}
__device__ __forceinline__ uint32_t pack_f16x2(float lo, float hi) {
    uint32_t p;
    asm("cvt.rn.f16x2.f32 %0, %1, %2;" : "=r"(p) : "f"(hi), "f"(lo));
    return p;
}
__device__ __forceinline__ uint32_t smem_u32(const void* p) {
    uint32_t a;
    asm("{ .reg .u64 t; cvta.to.shared.u64 t, %1; cvt.u32.u64 %0, t; }" : "=r"(a) : "l"(p));
    return a;
}
#define CP_ASYNC16(sdst, gsrc) \
    asm volatile("cp.async.cg.shared.global [%0], [%1], 16;" :: "r"(sdst), "l"(gsrc))
#define CP_COMMIT() asm volatile("cp.async.commit_group;")
#define CP_WAIT0()  asm volatile("cp.async.wait_group 0;")

// ================= prep: K/V -> fragment-order scratch =================
__global__ void __launch_bounds__(128) k_prep()
{
    int t = blockIdx.x, bh = blockIdx.y;
    int tid = threadIdx.x, lane = tid & 31, w = tid >> 5;
    int g = lane >> 2, tg = lane & 3;
    const float* kb = g_k + (size_t)bh * S1 * HD;
    const float* vb = g_v + (size_t)bh * S1 * HD;
    float*    kp = g_kp + ((size_t)bh * NTK + t) * KP_TILE;
    uint32_t* vp = g_vp + ((size_t)bh * NTK + t) * VP_TILE;

    for (int c = w; c < 32; c += 4) {
        if (c < 20) {                       // K combos: kt 0..4, j 0..3
            int kt = c >> 2, j = c & 3;
            float4 val;
            float* vv = (float*)&val;
            #pragma unroll
            for (int e = 0; e < 4; e++) {
                int idx = j * 4 + e, nt = idx >> 1, reg = idx & 1;
                int key = t * KT + g + 8 * nt;
                int col = tg + 4 * reg + 8 * kt;
                vv[e] = (key < S1) ? to_tf32(kb[(size_t)key * HD + col]) : 0.f;
            }
            ((float4*)kp)[(kt * 4 + j) * 32 + lane] = val;
        } else {                            // V combos: kt 0..3, j 0..2
            int cc = c - 20, kt = cc / 3, j = cc % 3;
            uint4 val;
            uint32_t* vv = (uint32_t*)&val;
            #pragma unroll
            for (int e = 0; e < 4; e++) {
                int idx = j * 4 + e, nt = idx >> 1, reg = idx & 1;
                int p = 8 * kt + tg + 4 * reg;   // key-pair index
                int d = g + 8 * nt;              // output dim (40=ones col)
                uint32_t r;
                if (d == 40) r = 0x3C003C00u;
                else if (d > 40) r = 0u;
                else {
                    int k0 = t * KT + 2 * p;
                    float v0 = (k0     < S1) ? vb[(size_t)k0 * HD + d]       : 0.f;
                    float v1 = (k0 + 1 < S1) ? vb[(size_t)(k0 + 1) * HD + d] : 0.f;
                    r = pack_f16x2(v0, v1);
                }
                vv[e] = r;
            }
            ((uint4*)vp)[(kt * 3 + j) * 32 + lane] = val;
        }
    }
}

// ================= flash attention v4: 8 warps, 16 rows/warp, no spills =====
__global__ void __launch_bounds__(256) k_flash4()
{
    __shared__ uint4 buf[2][1024];          // per tile: K 640 uint4 | V 384 uint4

    const int tid = threadIdx.x, w = tid >> 5, lane = tid & 31;
    const int g = lane >> 2, tg = lane & 3;
    const int qt = blockIdx.x, bh = blockIdx.y;

    const float*    qb = g_q  + (size_t)bh * S1 * HD;
    const float*    kp = g_kp + (size_t)bh * NTK * KP_TILE;
    const uint32_t* vp = g_vp + (size_t)bh * NTK * VP_TILE;

    // ---- Q fragments (16 rows per warp: r0, r0+8) ----
    const int r0 = qt * 128 + w * 16 + g;
    uint32_t qa[5][4];
    #pragma unroll
    for (int kt = 0; kt < 5; kt++) {
        qa[kt][0] = __float_as_uint(to_tf32(qb[(size_t)r0 * HD + tg + 8 * kt] * 0.158113883f));
        qa[kt][1] = __float_as_uint(to_tf32(qb[(size_t)(r0 + 8) * HD + tg + 8 * kt] * 0.158113883f));
        qa[kt][2] = __float_as_uint(to_tf32(qb[(size_t)r0 * HD + tg + 4 + 8 * kt] * 0.158113883f));
        qa[kt][3] = __float_as_uint(to_tf32(qb[(size_t)(r0 + 8) * HD + tg + 4 + 8 * kt] * 0.158113883f));
    }

    float o[6][4];
    #pragma unroll
    for (int b = 0; b < 6; b++)
        #pragma unroll
        for (int c = 0; c < 4; c++) o[b][c] = 0.f;
    float m[2] = { -1e30f, -1e30f };

    const uint32_t sb0 = smem_u32(&buf[0][0]);
    const uint32_t sb1 = smem_u32(&buf[1][0]);
    const char* kg0 = (const char*)kp;
    const char* vg0 = (const char*)vp;

    // prefetch tile 0 (1024 uint4 / 256 threads = 4 each)
    #pragma unroll
    for (int i = 0; i < 4; i++) {
        int idx = tid + i * 256;
        if (idx < 640) CP_ASYNC16(sb0 + idx * 16, kg0 + (size_t)idx * 16);
        else           CP_ASYNC16(sb0 + idx * 16, vg0 + (size_t)(idx - 640) * 16);
    }
    CP_COMMIT();

    for (int t = 0; t < NTK; t++) {
        CP_WAIT0();
        __syncthreads();

        if (t + 1 < NTK) {
            uint32_t sd = ((t + 1) & 1) ? sb1 : sb0;
            const char* kg = kg0 + (size_t)(t + 1) * KP_TILE * 4;
            const char* vg = vg0 + (size_t)(t + 1) * VP_TILE * 4;
            #pragma unroll
            for (int i = 0; i < 4; i++) {
                int idx = tid + i * 256;
                if (idx < 640) CP_ASYNC16(sd + idx * 16, kg + (size_t)idx * 16);
                else           CP_ASYNC16(sd + idx * 16, vg + (size_t)(idx - 640) * 16);
            }
            CP_COMMIT();
        }

        const float4* K4 = (const float4*)((t & 1) ? &buf[1][0] : &buf[0][0]);
        const uint4*  V4 = (const uint4*)(((t & 1) ? &buf[1][0] : &buf[0][0]) + 640);

        // ---- S = Q K^T ----
        float s[8][4];
        #pragma unroll
        for (int b = 0; b < 8; b++)
            #pragma unroll
            for (int c = 0; c < 4; c++) s[b][c] = 0.f;

        #pragma unroll
        for (int kt = 0; kt < 5; kt++) {
            float4 f0 = K4[(kt * 4 + 0) * 32 + lane];
            float4 f1 = K4[(kt * 4 + 1) * 32 + lane];
            float4 f2 = K4[(kt * 4 + 2) * 32 + lane];
            float4 f3 = K4[(kt * 4 + 3) * 32 + lane];
            uint32_t bb[8][2];
            bb[0][0] = __float_as_uint(f0.x); bb[0][1] = __float_as_uint(f0.y);
            bb[1][0] = __float_as_uint(f0.z); bb[1][1] = __float_as_uint(f0.w);
            bb[2][0] = __float_as_uint(f1.x); bb[2][1] = __float_as_uint(f1.y);
            bb[3][0] = __float_as_uint(f1.z); bb[3][1] = __float_as_uint(f1.w);
            bb[4][0] = __float_as_uint(f2.x); bb[4][1] = __float_as_uint(f2.y);
            bb[5][0] = __float_as_uint(f2.z); bb[5][1] = __float_as_uint(f2.w);
            bb[6][0] = __float_as_uint(f3.x); bb[6][1] = __float_as_uint(f3.y);
            bb[7][0] = __float_as_uint(f3.z); bb[7][1] = __float_as_uint(f3.w);
            #pragma unroll
            for (int nt = 0; nt < 8; nt++) mma_tf32(s[nt], qa[kt], bb[nt]);
        }

        // ---- mask invalid keys (last tile only) ----
        if (t == NTK - 1) {
            #pragma unroll
            for (int nt = 0; nt < 8; nt++) {
                int base = t * KT + 8 * nt + 2 * tg;
                if (base     >= S1) { s[nt][0] = s[nt][2] = -1e30f; }
                if (base + 1 >= S1) { s[nt][1] = s[nt][3] = -1e30f; }
            }
        }

        // ---- online softmax (2 row-halves) ----
        float corr[2], mL[2];
        #pragma unroll
        for (int r = 0; r < 2; r++) {
            float mx = -1e30f;
            #pragma unroll
            for (int nt = 0; nt < 8; nt++) {
                mx = fmaxf(mx, s[nt][2 * r]);
                mx = fmaxf(mx, s[nt][2 * r + 1]);
            }
            mx = fmaxf(mx, __shfl_xor_sync(0xFFFFFFFFu, mx, 1));
            mx = fmaxf(mx, __shfl_xor_sync(0xFFFFFFFFu, mx, 2));
            float mn = fmaxf(m[r], mx);
            corr[r] = __expf(m[r] - mn);
            m[r] = mn;
            mL[r] = mn * L2E;
        }

        #pragma unroll
        for (int nt = 0; nt < 6; nt++) {
            o[nt][0] *= corr[0];
            o[nt][1] *= corr[0];
            o[nt][2] *= corr[1];
            o[nt][3] *= corr[1];
        }

        uint32_t pf[8][2];
        #pragma unroll
        for (int nt = 0; nt < 8; nt++) {
            float f0 = __fmaf_rn(s[nt][0], L2E, -mL[0]);
            float f1 = __fmaf_rn(s[nt][1], L2E, -mL[0]);
            float f2 = __fmaf_rn(s[nt][2], L2E, -mL[1]);
            float f3 = __fmaf_rn(s[nt][3], L2E, -mL[1]);
            pf[nt][0] = pack_ex2_f16x2(f0, f1);
            pf[nt][1] = pack_ex2_f16x2(f2, f3);
        }

        // ---- O += P V ----
        #pragma unroll
        for (int kt = 0; kt < 4; kt++) {
            uint4 b0 = V4[(kt * 3 + 0) * 32 + lane];
            uint4 b1 = V4[(kt * 3 + 1) * 32 + lane];
            uint4 b2 = V4[(kt * 3 + 2) * 32 + lane];
            uint32_t bb[6][2];
            bb[0][0] = b0.x; bb[0][1] = b0.y;
            bb[1][0] = b0.z; bb[1][1] = b0.w;
            bb[2][0] = b1.x; bb[2][1] = b1.y;
            bb[3][0] = b1.z; bb[3][1] = b1.w;
            bb[4][0] = b2.x; bb[4][1] = b2.y;
            bb[5][0] = b2.z; bb[5][1] = b2.w;
            uint32_t aa[4] = { pf[2 * kt][0], pf[2 * kt][1],
                               pf[2 * kt + 1][0], pf[2 * kt + 1][1] };
            #pragma unroll
            for (int nt = 0; nt < 6; nt++) mma_f16(o[nt], aa, bb[nt]);
        }
    }

    // ---- epilogue: l from ones-column, normalize, store ----
    {
        float l0 = __shfl_sync(0xFFFFFFFFu, o[5][0], lane & ~3);
        float l1 = __shfl_sync(0xFFFFFFFFu, o[5][2], lane & ~3);
        float inv0 = 1.f / l0, inv1 = 1.f / l1;
        float* ob0 = g_att + ((size_t)bh * S1 + r0) * HD;
        float* ob1 = g_att + ((size_t)bh * S1 + r0 + 8) * HD;
        #pragma unroll
        for (int nt = 0; nt < 5; nt++) {
            int d = 8 * nt + 2 * tg;
            *(float2*)(ob0 + d) = make_float2(o[nt][0] * inv0, o[nt][1] * inv0);
            *(float2*)(ob1 + d) = make_float2(o[nt][2] * inv1, o[nt][3] * inv1);
        }
    }
}

// ================= conv =================
__global__ void k_conv(const float* __restrict__ x,
                       const float* __restrict__ w1, const float* __restrict__ b1,
                       const float* __restrict__ w2, const float* __restrict__ b2,
                       const float* __restrict__ pe)
{
    int j = blockIdx.x, i = blockIdx.y, b = blockIdx.z;
    int tid = threadIdx.x;
    __shared__ __align__(16) float patch[256];
    __shared__ __align__(16) float out1[64];
    for (int t = tid; t < 256; t += 160) {
        int c0 = t >> 2, k = t & 3, ky = k >> 1, kx = k & 1;
        patch[t] = x[((b * 64 + c0) * 128 + (2 * i + ky)) * 128 + (2 * j + kx)];
    }
    __syncthreads();
    if (tid < 64) {
        const float4* p4 = (const float4*)patch;
        const float4* w4 = (const float4*)(w1 + tid * 256);
        float4 a = make_float4(0.f, 0.f, 0.f, 0.f);
        #pragma unroll
        for (int c0 = 0; c0 < 64; c0++) {
            float4 pv = p4[c0], wv = w4[c0];
            a.x += pv.x * wv.x; a.y += pv.y * wv.y;
            a.z += pv.z * wv.z; a.w += pv.w * wv.w;
        }
        out1[tid] = b1[tid] + a.x + a.y + a.z + a.w;
    }
    __syncthreads();
    const float4* o4 = (const float4*)out1;
    const float4* w24 = (const float4*)(w2 + tid * 64);
    float4 a = make_float4(0.f, 0.f, 0.f, 0.f);
    #pragma unroll
    for (int c1 = 0; c1 < 16; c1++) {
        float4 ov = o4[c1], wv = w24[c1];
        a.x += ov.x * wv.x; a.y += ov.y * wv.y;
        a.z += ov.z * wv.z; a.w += ov.w * wv.w;
    }
    float acc = b2[tid] + a.x + a.y + a.z + a.w;
    acc = (acc >= 0.f) ? acc : 0.01f * acc;
    int s = i * 64 + j;
    g_f[((size_t)b * S1 + s) * DM + tid] = acc + pe[s];
}

__global__ void k_pad(const float* __restrict__ pe)
{
    int t = blockIdx.x * blockDim.x + threadIdx.x;
    if (t < BATCH * DM) {
        int b = t / DM, c = t % DM;
        g_f[((size_t)b * S1 + SMAX) * DM + c] = pe[SMAX];
    }
}

// ================= QKV projection (smem-tiled GEMM) =================
__global__ void __launch_bounds__(512) k_qkv(const float* __restrict__ wq,
                                             const float* __restrict__ wk,
                                             const float* __restrict__ wv)
{
    __shared__ float fsT[160 * 33];
    __shared__ float wsT[40 * 161];
    const int NROWS = BATCH * S1;
    int row0 = blockIdx.x * 32;
    const float* w = (blockIdx.y == 0) ? wq : ((blockIdx.y == 1) ? wk : wv);
    float* outp = (blockIdx.y == 0) ? g_q : ((blockIdx.y == 1) ? g_k : g_v);
    int tid = threadIdx.x;

    for (int idx = tid; idx < 32 * DM; idx += 512) {
        int mm = idx / DM, c = idx % DM;
        int gr = row0 + mm;
        fsT[c * 33 + mm] = (gr < NROWS) ? g_f[(size_t)gr * DM + c] : 0.f;
    }

    int tn = tid & 31;
    int tm = tid >> 5;
    int n0 = tn * 5;
    int m0 = tm * 2;
    float acc[2][5] = {};

    for (int c4 = 0; c4 < 4; c4++) {
        __syncthreads();
        for (int idx = tid; idx < DM * 40; idx += 512) {
            int n = idx / 40, kk = idx % 40;
            wsT[kk * 161 + n] = w[n * DM + c4 * 40 + kk];
        }
        __syncthreads();
        #pragma unroll 4
        for (int kk = 0; kk < 40; kk++) {
            int k = c4 * 40 + kk;
            float f0 = fsT[k * 33 + m0];
            float f1 = fsT[k * 33 + m0 + 1];
            #pragma unroll
            for (int i = 0; i < 5; i++) {
                float wv_ = wsT[kk * 161 + n0 + i];
                acc[0][i] = __fmaf_rn(f0, wv_, acc[0][i]);
                acc[1][i] = __fmaf_rn(f1, wv_, acc[1][i]);
            }
        }
    }

    #pragma unroll
    for (int mi = 0; mi < 2; mi++) {
        int gr = row0 + m0 + mi;
        if (gr >= NROWS) continue;
        int b = gr / S1, s = gr % S1;
        #pragma unroll
        for (int i = 0; i < 5; i++) {
            int n = n0 + i;
            int h = n / HD, d = n % HD;
            outp[(((size_t)b * NH + h) * S1 + s) * HD + d] = acc[mi][i];
        }
    }
}

// ================= LN stats =================
__global__ void k_stats()
{
    int r = blockIdx.x;
    int b = r >> 12, s = r & 4095;
    int tid = threadIdx.x;
    float v = 0.f;
    if (tid < DM) {
        int h = tid / HD, d = tid % HD;
        v = g_att[(((size_t)b * NH + h) * S1 + s) * HD + d];
    }
    __shared__ float r1[256], r2[256];
    r1[tid] = v; r2[tid] = v * v;
    __syncthreads();
    for (int off = 128; off > 0; off >>= 1) {
        if (tid < off) { r1[tid] += r1[tid + off]; r2[tid] += r2[tid + off]; }
        __syncthreads();
    }
    if (tid == 0) {
        float mean = r1[0] * (1.f / DM);
        float var  = r2[0] * (1.f / DM) - mean * mean;
        g_stats[2 * r]     = mean;
        g_stats[2 * r + 1] = rsqrtf(var + 1e-5f);
    }
}

// ================= LN + residual + upsample =================
__global__ void k_out(const float* __restrict__ ln_w, const float* __restrict__ ln_b,
                      float* __restrict__ out)
{
    int tx = threadIdx.x, ty = threadIdx.y;
    int j = blockIdx.x * 32 + tx;
    int i = blockIdx.y;
    int bz = blockIdx.z;
    int b = bz / 20, cg = bz % 20;
    int c = cg * 8 + ty;
    int s = i * 64 + j;
    int h = c / HD, d = c % HD;
    float v = g_att[(((size_t)b * NH + h) * S1 + s) * HD + d];
    float mean = g_stats[2 * (b * SMAX + s)];
    float rstd = g_stats[2 * (b * SMAX + s) + 1];
    float ln = (v - mean) * rstd * ln_w[c] + ln_b[c];
    float ov = ln + v;
    size_t base = (((size_t)b * DM + c) * 128 + 2 * i) * 128 + 2 * j;
    float2 v2 = make_float2(ov, ov);
    *(float2*)(out + base)       = v2;
    *(float2*)(out + base + 128) = v2;
}

// ---------------- launch ----------------
extern "C" void kernel_launch(void* const* d_in, const int* in_sizes, int n_in,
                              void* d_out, int out_size)
{
    const float* x   = (const float*)d_in[0];
    const float* w1  = (const float*)d_in[1];
    const float* b1  = (const float*)d_in[2];
    const float* w2  = (const float*)d_in[3];
    const float* b2  = (const float*)d_in[4];
    const float* pe  = (const float*)d_in[5];
    const float* wq  = (const float*)d_in[6];
    const float* wk  = (const float*)d_in[7];
    const float* wv  = (const float*)d_in[8];
    const float* lnw = (const float*)d_in[9];
    const float* lnb = (const float*)d_in[10];
    float* out = (float*)d_out;

    k_conv<<<dim3(64, 64, BATCH), 160>>>(x, w1, b1, w2, b2, pe);
    k_pad<<<1, BATCH * DM>>>(pe);
    k_qkv<<<dim3((BATCH * S1 + 31) / 32, 3), 512>>>(wq, wk, wv);
    k_prep<<<dim3(NTK, BATCH * NH), 128>>>();
    k_flash4<<<dim3(SMAX / 128, BATCH * NH), 256>>>();
    k_stats<<<BATCH * SMAX, 256>>>();
    k_out<<<dim3(2, 64, BATCH * 20), dim3(32, 8)>>>(lnw, lnb, out);
}

// round 9
// speedup vs baseline: 3.3415x; 1.8778x over previous
#include <cuda_runtime.h>
#include <cuda_fp16.h>
#include <cuda_bf16.h>
#include <cstdint>

#define S1 4097
#define SMAX 4096
#define DM 160
#define NH 4
#define HD 40
#define BATCH 4
#define KT 64
#define NTK 65           // ceil(4097/64)
#define L2E 1.4426950408889634f
#define KP_TILE 2560     // floats per K fragment tile
#define VP_TILE 1536     // u32 per V fragment tile

// ---------------- device scratch ----------------
__device__ float g_f[BATCH * S1 * DM];
__device__ float g_q[BATCH * NH * S1 * HD];
__device__ float g_k[BATCH * NH * S1 * HD];
__device__ float g_v[BATCH * NH * S1 * HD];
__device__ float g_att[BATCH * NH * S1 * HD];
__device__ float g_stats[BATCH * SMAX * 2];
__device__ float    g_kp[BATCH * NH * NTK * KP_TILE];
__device__ uint32_t g_vp[BATCH * NH * NTK * VP_TILE];

// ---------------- helpers ----------------
__device__ __forceinline__ void mma_tf32(float* c, const uint32_t* a, const uint32_t* b) {
    asm volatile(
        "mma.sync.aligned.m16n8k8.row.col.f32.tf32.tf32.f32 "
        "{%0,%1,%2,%3}, {%4,%5,%6,%7}, {%8,%9}, {%0,%1,%2,%3};"
        : "+f"(c[0]), "+f"(c[1]), "+f"(c[2]), "+f"(c[3])
        : "r"(a[0]), "r"(a[1]), "r"(a[2]), "r"(a[3]), "r"(b[0]), "r"(b[1]));
}
__device__ __forceinline__ void mma_f16(float* c, const uint32_t* a, const uint32_t* b) {
    asm volatile(
        "mma.sync.aligned.m16n8k16.row.col.f32.f16.f16.f32 "
        "{%0,%1,%2,%3}, {%4,%5,%6,%7}, {%8,%9}, {%0,%1,%2,%3};"
        : "+f"(c[0]), "+f"(c[1]), "+f"(c[2]), "+f"(c[3])
        : "r"(a[0]), "r"(a[1]), "r"(a[2]), "r"(a[3]), "r"(b[0]), "r"(b[1]));
}
__device__ __forceinline__ float to_tf32(float x) {
    float r;
    asm("cvt.rna.tf32.f32 %0, %1;" : "=f"(r) : "f"(x));
    return r;
}
__device__ __forceinline__ uint32_t pack_ex2_f16x2(float lo, float hi) {
    uint32_t p, r;
    asm("cvt.rn.f16x2.f32 %0, %1, %2;" : "=r"(p) : "f"(hi), "f"(lo));
    asm("ex2.approx.f16x2 %0, %1;" : "=r"(r) : "r"(p));
    return r;
}
__device__ __forceinline__ uint32_t pack_f16x2(float lo, float hi) {
    uint32_t p;
    asm("cvt.rn.f16x2.f32 %0, %1, %2;" : "=r"(p) : "f"(hi), "f"(lo));
    return p;
}
__device__ __forceinline__ uint32_t smem_u32(const void* p) {
    uint32_t a;
    asm("{ .reg .u64 t; cvta.to.shared.u64 t, %1; cvt.u32.u64 %0, t; }" : "=r"(a) : "l"(p));
    return a;
}
#define CP_ASYNC16(sdst, gsrc) \
    asm volatile("cp.async.cg.shared.global [%0], [%1], 16;" :: "r"(sdst), "l"(gsrc))
#define CP_COMMIT() asm volatile("cp.async.commit_group;")
#define CP_WAIT0()  asm volatile("cp.async.wait_group 0;")

// ================= prep: K/V -> fragment-order scratch =================
__global__ void __launch_bounds__(128) k_prep()
{
    int t = blockIdx.x, bh = blockIdx.y;
    int tid = threadIdx.x, lane = tid & 31, w = tid >> 5;
    int g = lane >> 2, tg = lane & 3;
    const float* kb = g_k + (size_t)bh * S1 * HD;
    const float* vb = g_v + (size_t)bh * S1 * HD;
    float*    kp = g_kp + ((size_t)bh * NTK + t) * KP_TILE;
    uint32_t* vp = g_vp + ((size_t)bh * NTK + t) * VP_TILE;

    for (int c = w; c < 32; c += 4) {
        if (c < 20) {
            int kt = c >> 2, j = c & 3;
            float4 val;
            float* vv = (float*)&val;
            #pragma unroll
            for (int e = 0; e < 4; e++) {
                int idx = j * 4 + e, nt = idx >> 1, reg = idx & 1;
                int key = t * KT + g + 8 * nt;
                int col = tg + 4 * reg + 8 * kt;
                vv[e] = (key < S1) ? to_tf32(kb[(size_t)key * HD + col]) : 0.f;
            }
            ((float4*)kp)[(kt * 4 + j) * 32 + lane] = val;
        } else {
            int cc = c - 20, kt = cc / 3, j = cc % 3;
            uint4 val;
            uint32_t* vv = (uint32_t*)&val;
            #pragma unroll
            for (int e = 0; e < 4; e++) {
                int idx = j * 4 + e, nt = idx >> 1, reg = idx & 1;
                int p = 8 * kt + tg + 4 * reg;
                int d = g + 8 * nt;
                uint32_t r;
                if (d == 40) r = 0x3C003C00u;
                else if (d > 40) r = 0u;
                else {
                    int k0 = t * KT + 2 * p;
                    float v0 = (k0     < S1) ? vb[(size_t)k0 * HD + d]       : 0.f;
                    float v1 = (k0 + 1 < S1) ? vb[(size_t)(k0 + 1) * HD + d] : 0.f;
                    r = pack_f16x2(v0, v1);
                }
                vv[e] = r;
            }
            ((uint4*)vp)[(kt * 3 + j) * 32 + lane] = val;
        }
    }
}

// ================= flash attention v4 (unchanged from round 8 WIN) ==========
__global__ void __launch_bounds__(256) k_flash4()
{
    __shared__ uint4 buf[2][1024];

    const int tid = threadIdx.x, w = tid >> 5, lane = tid & 31;
    const int g = lane >> 2, tg = lane & 3;
    const int qt = blockIdx.x, bh = blockIdx.y;

    const float*    qb = g_q  + (size_t)bh * S1 * HD;
    const float*    kp = g_kp + (size_t)bh * NTK * KP_TILE;
    const uint32_t* vp = g_vp + (size_t)bh * NTK * VP_TILE;

    const int r0 = qt * 128 + w * 16 + g;
    uint32_t qa[5][4];
    #pragma unroll
    for (int kt = 0; kt < 5; kt++) {
        qa[kt][0] = __float_as_uint(to_tf32(qb[(size_t)r0 * HD + tg + 8 * kt] * 0.158113883f));
        qa[kt][1] = __float_as_uint(to_tf32(qb[(size_t)(r0 + 8) * HD + tg + 8 * kt] * 0.158113883f));
        qa[kt][2] = __float_as_uint(to_tf32(qb[(size_t)r0 * HD + tg + 4 + 8 * kt] * 0.158113883f));
        qa[kt][3] = __float_as_uint(to_tf32(qb[(size_t)(r0 + 8) * HD + tg + 4 + 8 * kt] * 0.158113883f));
    }

    float o[6][4];
    #pragma unroll
    for (int b = 0; b < 6; b++)
        #pragma unroll
        for (int c = 0; c < 4; c++) o[b][c] = 0.f;
    float m[2] = { -1e30f, -1e30f };

    const uint32_t sb0 = smem_u32(&buf[0][0]);
    const uint32_t sb1 = smem_u32(&buf[1][0]);
    const char* kg0 = (const char*)kp;
    const char* vg0 = (const char*)vp;

    #pragma unroll
    for (int i = 0; i < 4; i++) {
        int idx = tid + i * 256;
        if (idx < 640) CP_ASYNC16(sb0 + idx * 16, kg0 + (size_t)idx * 16);
        else           CP_ASYNC16(sb0 + idx * 16, vg0 + (size_t)(idx - 640) * 16);
    }
    CP_COMMIT();

    for (int t = 0; t < NTK; t++) {
        CP_WAIT0();
        __syncthreads();

        if (t + 1 < NTK) {
            uint32_t sd = ((t + 1) & 1) ? sb1 : sb0;
            const char* kg = kg0 + (size_t)(t + 1) * KP_TILE * 4;
            const char* vg = vg0 + (size_t)(t + 1) * VP_TILE * 4;
            #pragma unroll
            for (int i = 0; i < 4; i++) {
                int idx = tid + i * 256;
                if (idx < 640) CP_ASYNC16(sd + idx * 16, kg + (size_t)idx * 16);
                else           CP_ASYNC16(sd + idx * 16, vg + (size_t)(idx - 640) * 16);
            }
            CP_COMMIT();
        }

        const float4* K4 = (const float4*)((t & 1) ? &buf[1][0] : &buf[0][0]);
        const uint4*  V4 = (const uint4*)(((t & 1) ? &buf[1][0] : &buf[0][0]) + 640);

        float s[8][4];
        #pragma unroll
        for (int b = 0; b < 8; b++)
            #pragma unroll
            for (int c = 0; c < 4; c++) s[b][c] = 0.f;

        #pragma unroll
        for (int kt = 0; kt < 5; kt++) {
            float4 f0 = K4[(kt * 4 + 0) * 32 + lane];
            float4 f1 = K4[(kt * 4 + 1) * 32 + lane];
            float4 f2 = K4[(kt * 4 + 2) * 32 + lane];
            float4 f3 = K4[(kt * 4 + 3) * 32 + lane];
            uint32_t bb[8][2];
            bb[0][0] = __float_as_uint(f0.x); bb[0][1] = __float_as_uint(f0.y);
            bb[1][0] = __float_as_uint(f0.z); bb[1][1] = __float_as_uint(f0.w);
            bb[2][0] = __float_as_uint(f1.x); bb[2][1] = __float_as_uint(f1.y);
            bb[3][0] = __float_as_uint(f1.z); bb[3][1] = __float_as_uint(f1.w);
            bb[4][0] = __float_as_uint(f2.x); bb[4][1] = __float_as_uint(f2.y);
            bb[5][0] = __float_as_uint(f2.z); bb[5][1] = __float_as_uint(f2.w);
            bb[6][0] = __float_as_uint(f3.x); bb[6][1] = __float_as_uint(f3.y);
            bb[7][0] = __float_as_uint(f3.z); bb[7][1] = __float_as_uint(f3.w);
            #pragma unroll
            for (int nt = 0; nt < 8; nt++) mma_tf32(s[nt], qa[kt], bb[nt]);
        }

        if (t == NTK - 1) {
            #pragma unroll
            for (int nt = 0; nt < 8; nt++) {
                int base = t * KT + 8 * nt + 2 * tg;
                if (base     >= S1) { s[nt][0] = s[nt][2] = -1e30f; }
                if (base + 1 >= S1) { s[nt][1] = s[nt][3] = -1e30f; }
            }
        }

        float corr[2], mL[2];
        #pragma unroll
        for (int r = 0; r < 2; r++) {
            float mx = -1e30f;
            #pragma unroll
            for (int nt = 0; nt < 8; nt++) {
                mx = fmaxf(mx, s[nt][2 * r]);
                mx = fmaxf(mx, s[nt][2 * r + 1]);
            }
            mx = fmaxf(mx, __shfl_xor_sync(0xFFFFFFFFu, mx, 1));
            mx = fmaxf(mx, __shfl_xor_sync(0xFFFFFFFFu, mx, 2));
            float mn = fmaxf(m[r], mx);
            corr[r] = __expf(m[r] - mn);
            m[r] = mn;
            mL[r] = mn * L2E;
        }

        #pragma unroll
        for (int nt = 0; nt < 6; nt++) {
            o[nt][0] *= corr[0];
            o[nt][1] *= corr[0];
            o[nt][2] *= corr[1];
            o[nt][3] *= corr[1];
        }

        uint32_t pf[8][2];
        #pragma unroll
        for (int nt = 0; nt < 8; nt++) {
            float f0 = __fmaf_rn(s[nt][0], L2E, -mL[0]);
            float f1 = __fmaf_rn(s[nt][1], L2E, -mL[0]);
            float f2 = __fmaf_rn(s[nt][2], L2E, -mL[1]);
            float f3 = __fmaf_rn(s[nt][3], L2E, -mL[1]);
            pf[nt][0] = pack_ex2_f16x2(f0, f1);
            pf[nt][1] = pack_ex2_f16x2(f2, f3);
        }

        #pragma unroll
        for (int kt = 0; kt < 4; kt++) {
            uint4 b0 = V4[(kt * 3 + 0) * 32 + lane];
            uint4 b1 = V4[(kt * 3 + 1) * 32 + lane];
            uint4 b2 = V4[(kt * 3 + 2) * 32 + lane];
            uint32_t bb[6][2];
            bb[0][0] = b0.x; bb[0][1] = b0.y;
            bb[1][0] = b0.z; bb[1][1] = b0.w;
            bb[2][0] = b1.x; bb[2][1] = b1.y;
            bb[3][0] = b1.z; bb[3][1] = b1.w;
            bb[4][0] = b2.x; bb[4][1] = b2.y;
            bb[5][0] = b2.z; bb[5][1] = b2.w;
            uint32_t aa[4] = { pf[2 * kt][0], pf[2 * kt][1],
                               pf[2 * kt + 1][0], pf[2 * kt + 1][1] };
            #pragma unroll
            for (int nt = 0; nt < 6; nt++) mma_f16(o[nt], aa, bb[nt]);
        }
    }

    {
        float l0 = __shfl_sync(0xFFFFFFFFu, o[5][0], lane & ~3);
        float l1 = __shfl_sync(0xFFFFFFFFu, o[5][2], lane & ~3);
        float inv0 = 1.f / l0, inv1 = 1.f / l1;
        float* ob0 = g_att + ((size_t)bh * S1 + r0) * HD;
        float* ob1 = g_att + ((size_t)bh * S1 + r0 + 8) * HD;
        #pragma unroll
        for (int nt = 0; nt < 5; nt++) {
            int d = 8 * nt + 2 * tg;
            *(float2*)(ob0 + d) = make_float2(o[nt][0] * inv0, o[nt][1] * inv0);
            *(float2*)(ob1 + d) = make_float2(o[nt][2] * inv1, o[nt][3] * inv1);
        }
    }
}

// ================= conv v2: one block per (row i, batch) ====================
// 256 threads. smem: xs[64][2][128] | w1s[64][256] | o1s[64][65] | w2T[64][164]
#define CONV_SMEM ((16384 + 16384 + 4160 + 10496) * 4)
__global__ void __launch_bounds__(256) k_conv2(const float* __restrict__ x,
                       const float* __restrict__ w1, const float* __restrict__ b1,
                       const float* __restrict__ w2, const float* __restrict__ b2,
                       const float* __restrict__ pe)
{
    extern __shared__ float cs[];
    float* xs  = cs;              // 16384
    float* w1s = cs + 16384;      // 16384
    float* o1s = cs + 32768;      // 64*65
    float* w2T = cs + 36928;      // 64*164

    const int i = blockIdx.x, b = blockIdx.y;
    const int tid = threadIdx.x;

    // stage A: load x rows (2i, 2i+1) for all 64 c0; w1; w2 transposed
    const float4* x4 = (const float4*)x;
    #pragma unroll
    for (int q = 0; q < 16; q++) {
        int idx = tid + q * 256;            // 4096 float4
        int c0 = idx >> 6, r = idx & 63, ky = r >> 5, w4 = r & 31;
        ((float4*)xs)[c0 * 64 + ky * 32 + w4] =
            x4[(size_t)((b * 64 + c0) * 128 + (2 * i + ky)) * 32 + w4];
    }
    #pragma unroll
    for (int q = 0; q < 16; q++) {
        int idx = tid + q * 256;
        ((float4*)w1s)[idx] = ((const float4*)w1)[idx];
    }
    for (int idx = tid; idx < 10240; idx += 256) {
        int c2 = idx >> 6, c1 = idx & 63;
        w2T[c1 * 164 + c2] = w2[idx];
    }
    __syncthreads();

    // stage B: conv1 — thread tile 4 j x 4 c1
    {
        const int j0  = (tid & 15) * 4;
        const int c10 = (tid >> 4) * 4;
        float a1[4][4] = {};
        #pragma unroll 4
        for (int c0 = 0; c0 < 64; c0++) {
            float4 wv[4];
            #pragma unroll
            for (int cc = 0; cc < 4; cc++)
                wv[cc] = *(float4*)&w1s[(c10 + cc) * 256 + c0 * 4];
            #pragma unroll
            for (int jj = 0; jj < 4; jj++) {
                float2 x0 = *(float2*)&xs[c0 * 256 + 2 * (j0 + jj)];
                float2 x1 = *(float2*)&xs[c0 * 256 + 128 + 2 * (j0 + jj)];
                #pragma unroll
                for (int cc = 0; cc < 4; cc++)
                    a1[jj][cc] += x0.x * wv[cc].x + x0.y * wv[cc].y
                                + x1.x * wv[cc].z + x1.y * wv[cc].w;
            }
        }
        #pragma unroll
        for (int jj = 0; jj < 4; jj++)
            #pragma unroll
            for (int cc = 0; cc < 4; cc++)
                o1s[(j0 + jj) * 65 + c10 + cc] = b1[c10 + cc] + a1[jj][cc];
    }
    __syncthreads();

    // stage C: conv2 + leaky + pe — thread tile 2 j x 20 c2
    {
        const int jj2 = tid & 31;           // j pair (2*jj2, 2*jj2+1)
        const int c20 = (tid >> 5) * 20;
        float a2[2][20] = {};
        #pragma unroll 4
        for (int c1 = 0; c1 < 64; c1++) {
            float p0 = o1s[(2 * jj2) * 65 + c1];
            float p1 = o1s[(2 * jj2 + 1) * 65 + c1];
            #pragma unroll
            for (int q = 0; q < 5; q++) {
                float4 wv = *(float4*)&w2T[c1 * 164 + c20 + q * 4];
                a2[0][q * 4 + 0] += p0 * wv.x; a2[1][q * 4 + 0] += p1 * wv.x;
                a2[0][q * 4 + 1] += p0 * wv.y; a2[1][q * 4 + 1] += p1 * wv.y;
                a2[0][q * 4 + 2] += p0 * wv.z; a2[1][q * 4 + 2] += p1 * wv.z;
                a2[0][q * 4 + 3] += p0 * wv.w; a2[1][q * 4 + 3] += p1 * wv.w;
            }
        }
        #pragma unroll
        for (int row = 0; row < 2; row++) {
            int j = 2 * jj2 + row;
            int s = i * 64 + j;
            float pev = pe[s];
            #pragma unroll
            for (int cc = 0; cc < 20; cc++) {
                int c2 = c20 + cc;
                float v = a2[row][cc] + b2[c2];
                v = (v >= 0.f) ? v : 0.01f * v;
                g_f[((size_t)b * S1 + s) * DM + c2] = v + pev;
            }
        }
    }
}

__global__ void k_pad(const float* __restrict__ pe)
{
    int t = blockIdx.x * blockDim.x + threadIdx.x;
    if (t < BATCH * DM) {
        int b = t / DM, c = t % DM;
        g_f[((size_t)b * S1 + SMAX) * DM + c] = pe[SMAX];
    }
}

// ================= QKV v2: 64-row tiles, 4x5 per-thread =====================
#define QKV_SMEM ((160 * 64 + 40 * 161) * 4)
__global__ void __launch_bounds__(512) k_qkv2(const float* __restrict__ wq,
                                              const float* __restrict__ wk,
                                              const float* __restrict__ wv)
{
    extern __shared__ float qs[];
    float* fsT = qs;               // [c][m] 160 x 64
    float* wsT = qs + 160 * 64;    // [kk][n] 40 x 161

    const int NROWS = BATCH * S1;
    int row0 = blockIdx.x * 64;
    const float* w = (blockIdx.y == 0) ? wq : ((blockIdx.y == 1) ? wk : wv);
    float* outp = (blockIdx.y == 0) ? g_q : ((blockIdx.y == 1) ? g_k : g_v);
    int tid = threadIdx.x;

    for (int idx = tid; idx < 64 * DM; idx += 512) {
        int mm = idx / DM, c = idx % DM;
        int gr = row0 + mm;
        fsT[c * 64 + mm] = (gr < NROWS) ? g_f[(size_t)gr * DM + c] : 0.f;
    }

    const int m0 = (tid >> 5) * 4;      // 16 warps x 4 rows
    const int n0 = (tid & 31) * 5;      // 32 lanes x 5 cols
    float acc[4][5] = {};

    for (int c4 = 0; c4 < 4; c4++) {
        __syncthreads();
        for (int idx = tid; idx < DM * 40; idx += 512) {
            int n = idx / 40, kk = idx % 40;
            wsT[kk * 161 + n] = w[n * DM + c4 * 40 + kk];
        }
        __syncthreads();
        #pragma unroll 4
        for (int kk = 0; kk < 40; kk++) {
            int k = c4 * 40 + kk;
            float4 fv = *(float4*)&fsT[k * 64 + m0];
            #pragma unroll
            for (int i = 0; i < 5; i++) {
                float wv_ = wsT[kk * 161 + n0 + i];
                acc[0][i] = __fmaf_rn(fv.x, wv_, acc[0][i]);
                acc[1][i] = __fmaf_rn(fv.y, wv_, acc[1][i]);
                acc[2][i] = __fmaf_rn(fv.z, wv_, acc[2][i]);
                acc[3][i] = __fmaf_rn(fv.w, wv_, acc[3][i]);
            }
        }
    }

    #pragma unroll
    for (int mi = 0; mi < 4; mi++) {
        int gr = row0 + m0 + mi;
        if (gr >= NROWS) continue;
        int b = gr / S1, s = gr % S1;
        #pragma unroll
        for (int i = 0; i < 5; i++) {
            int n = n0 + i;
            int h = n / HD, d = n % HD;
            outp[(((size_t)b * NH + h) * S1 + s) * HD + d] = acc[mi][i];
        }
    }
}

// ================= LN stats: one warp per row ===============================
__global__ void __launch_bounds__(256) k_stats2()
{
    int gw = blockIdx.x * 8 + (threadIdx.x >> 5);   // 0..16383
    int lane = threadIdx.x & 31;
    int b = gw >> 12, s = gw & 4095;

    float sum = 0.f, sq = 0.f;
    #pragma unroll
    for (int j = 0; j < 5; j++) {
        int c = lane + 32 * j;                      // 0..159
        int h = c / HD, d = c % HD;
        float v = g_att[(((size_t)b * NH + h) * S1 + s) * HD + d];
        sum += v; sq += v * v;
    }
    #pragma unroll
    for (int off = 16; off > 0; off >>= 1) {
        sum += __shfl_xor_sync(0xFFFFFFFFu, sum, off);
        sq  += __shfl_xor_sync(0xFFFFFFFFu, sq, off);
    }
    if (lane == 0) {
        float mean = sum * (1.f / DM);
        float var  = sq * (1.f / DM) - mean * mean;
        g_stats[2 * gw]     = mean;
        g_stats[2 * gw + 1] = rsqrtf(var + 1e-5f);
    }
}

// ================= LN + residual + upsample =================
__global__ void k_out(const float* __restrict__ ln_w, const float* __restrict__ ln_b,
                      float* __restrict__ out)
{
    int tx = threadIdx.x, ty = threadIdx.y;
    int j = blockIdx.x * 32 + tx;
    int i = blockIdx.y;
    int bz = blockIdx.z;
    int b = bz / 20, cg = bz % 20;
    int c = cg * 8 + ty;
    int s = i * 64 + j;
    int h = c / HD, d = c % HD;
    float v = g_att[(((size_t)b * NH + h) * S1 + s) * HD + d];
    float mean = g_stats[2 * (b * SMAX + s)];
    float rstd = g_stats[2 * (b * SMAX + s) + 1];
    float ln = (v - mean) * rstd * ln_w[c] + ln_b[c];
    float ov = ln + v;
    size_t base = (((size_t)b * DM + c) * 128 + 2 * i) * 128 + 2 * j;
    float2 v2 = make_float2(ov, ov);
    *(float2*)(out + base)       = v2;
    *(float2*)(out + base + 128) = v2;
}

// ---------------- launch ----------------
extern "C" void kernel_launch(void* const* d_in, const int* in_sizes, int n_in,
                              void* d_out, int out_size)
{
    const float* x   = (const float*)d_in[0];
    const float* w1  = (const float*)d_in[1];
    const float* b1  = (const float*)d_in[2];
    const float* w2  = (const float*)d_in[3];
    const float* b2  = (const float*)d_in[4];
    const float* pe  = (const float*)d_in[5];
    const float* wq  = (const float*)d_in[6];
    const float* wk  = (const float*)d_in[7];
    const float* wv  = (const float*)d_in[8];
    const float* lnw = (const float*)d_in[9];
    const float* lnb = (const float*)d_in[10];
    float* out = (float*)d_out;

    static int attr_set = 0;
    if (!attr_set) {
        cudaFuncSetAttribute(k_conv2, cudaFuncAttributeMaxDynamicSharedMemorySize, CONV_SMEM);
        cudaFuncSetAttribute(k_qkv2,  cudaFuncAttributeMaxDynamicSharedMemorySize, QKV_SMEM);
        attr_set = 1;
    }

    k_conv2<<<dim3(64, BATCH), 256, CONV_SMEM>>>(x, w1, b1, w2, b2, pe);
    k_pad<<<1, BATCH * DM>>>(pe);
    k_qkv2<<<dim3((BATCH * S1 + 63) / 64, 3), 512, QKV_SMEM>>>(wq, wk, wv);
    k_prep<<<dim3(NTK, BATCH * NH), 128>>>();
    k_flash4<<<dim3(SMAX / 128, BATCH * NH), 256>>>();
    k_stats2<<<BATCH * SMAX / 8, 256>>>();
    k_out<<<dim3(2, 64, BATCH * 20), dim3(32, 8)>>>(lnw, lnb, out);
}

// round 10
// speedup vs baseline: 3.6763x; 1.1002x over previous
#include <cuda_runtime.h>
#include <cuda_fp16.h>
#include <cuda_bf16.h>
#include <cstdint>

#define S1 4097
#define SMAX 4096
#define DM 160
#define NH 4
#define HD 40
#define BATCH 4
#define KT 64
#define NTK 65           // ceil(4097/64)
#define L2E 1.4426950408889634f
#define KP_TILE 1536     // u32 per K fragment tile (3kt*4j*32lane*4) bf16x2
#define VP_TILE 1536     // u32 per V fragment tile (4kt*3j*32lane*4) f16x2

// ---------------- device scratch ----------------
__device__ float g_f[BATCH * S1 * DM];
__device__ float g_q[BATCH * NH * S1 * HD];
__device__ float g_k[BATCH * NH * S1 * HD];
__device__ float g_v[BATCH * NH * S1 * HD];
__device__ float g_att[BATCH * NH * S1 * HD];
__device__ float g_stats[BATCH * SMAX * 2];
__device__ uint32_t g_kp[BATCH * NH * NTK * KP_TILE];   // K in bf16 B-frag order
__device__ uint32_t g_vp[BATCH * NH * NTK * VP_TILE];   // V in f16 B-frag order

// ---------------- helpers ----------------
__device__ __forceinline__ void mma_bf16(float* c, const uint32_t* a, const uint32_t* b) {
    asm volatile(
        "mma.sync.aligned.m16n8k16.row.col.f32.bf16.bf16.f32 "
        "{%0,%1,%2,%3}, {%4,%5,%6,%7}, {%8,%9}, {%0,%1,%2,%3};"
        : "+f"(c[0]), "+f"(c[1]), "+f"(c[2]), "+f"(c[3])
        : "r"(a[0]), "r"(a[1]), "r"(a[2]), "r"(a[3]), "r"(b[0]), "r"(b[1]));
}
__device__ __forceinline__ void mma_f16(float* c, const uint32_t* a, const uint32_t* b) {
    asm volatile(
        "mma.sync.aligned.m16n8k16.row.col.f32.f16.f16.f32 "
        "{%0,%1,%2,%3}, {%4,%5,%6,%7}, {%8,%9}, {%0,%1,%2,%3};"
        : "+f"(c[0]), "+f"(c[1]), "+f"(c[2]), "+f"(c[3])
        : "r"(a[0]), "r"(a[1]), "r"(a[2]), "r"(a[3]), "r"(b[0]), "r"(b[1]));
}
__device__ __forceinline__ uint32_t pack_bf16x2(float lo, float hi) {
    uint32_t p;
    asm("cvt.rn.bf16x2.f32 %0, %1, %2;" : "=r"(p) : "f"(hi), "f"(lo));
    return p;
}
__device__ __forceinline__ uint32_t pack_ex2_f16x2(float lo, float hi) {
    uint32_t p, r;
    asm("cvt.rn.f16x2.f32 %0, %1, %2;" : "=r"(p) : "f"(hi), "f"(lo));
    asm("ex2.approx.f16x2 %0, %1;" : "=r"(r) : "r"(p));
    return r;
}
__device__ __forceinline__ uint32_t pack_f16x2(float lo, float hi) {
    uint32_t p;
    asm("cvt.rn.f16x2.f32 %0, %1, %2;" : "=r"(p) : "f"(hi), "f"(lo));
    return p;
}
__device__ __forceinline__ uint32_t smem_u32(const void* p) {
    uint32_t a;
    asm("{ .reg .u64 t; cvta.to.shared.u64 t, %1; cvt.u32.u64 %0, t; }" : "=r"(a) : "l"(p));
    return a;
}
#define CP_ASYNC16(sdst, gsrc) \
    asm volatile("cp.async.cg.shared.global [%0], [%1], 16;" :: "r"(sdst), "l"(gsrc))
#define CP_COMMIT() asm volatile("cp.async.commit_group;")
#define CP_WAIT0()  asm volatile("cp.async.wait_group 0;")

// ================= prep: K(bf16)/V(f16) -> fragment-order scratch ===========
// grid (NTK, 16), 128 threads. Tile = 64 keys.
// K frag (m16n8k16 B): reg0 = keys? no — B[n=key][k=col]:
//   (kt,j) uint4 elems e: idx=j*4+e, nt=idx>>1, reg=idx&1
//   value = bf16x2( K[key g+8nt][16kt+2(tg+4reg)], K[..][col+1] ), col>=40 -> 0
__global__ void __launch_bounds__(128) k_prep()
{
    int t = blockIdx.x, bh = blockIdx.y;
    int tid = threadIdx.x, lane = tid & 31, w = tid >> 5;
    int g = lane >> 2, tg = lane & 3;
    const float* kb = g_k + (size_t)bh * S1 * HD;
    const float* vb = g_v + (size_t)bh * S1 * HD;
    uint32_t* kp = g_kp + ((size_t)bh * NTK + t) * KP_TILE;
    uint32_t* vp = g_vp + ((size_t)bh * NTK + t) * VP_TILE;

    for (int c = w; c < 24; c += 4) {
        if (c < 12) {                       // K combos: kt 0..2, j 0..3
            int kt = c >> 2, j = c & 3;
            uint4 val;
            uint32_t* vv = (uint32_t*)&val;
            #pragma unroll
            for (int e = 0; e < 4; e++) {
                int idx = j * 4 + e, nt = idx >> 1, reg = idx & 1;
                int key = t * KT + g + 8 * nt;
                int col = 16 * kt + 2 * (tg + 4 * reg);
                float v0 = (key < S1 && col     < HD) ? kb[(size_t)key * HD + col]     : 0.f;
                float v1 = (key < S1 && col + 1 < HD) ? kb[(size_t)key * HD + col + 1] : 0.f;
                vv[e] = pack_bf16x2(v0, v1);
            }
            ((uint4*)kp)[(kt * 4 + j) * 32 + lane] = val;
        } else {                            // V combos: kt 0..3, j 0..2
            int cc = c - 12, kt = cc / 3, j = cc % 3;
            uint4 val;
            uint32_t* vv = (uint32_t*)&val;
            #pragma unroll
            for (int e = 0; e < 4; e++) {
                int idx = j * 4 + e, nt = idx >> 1, reg = idx & 1;
                int p = 8 * kt + tg + 4 * reg;   // key-pair index
                int d = g + 8 * nt;              // output dim (40=ones col)
                uint32_t r;
                if (d == 40) r = 0x3C003C00u;
                else if (d > 40) r = 0u;
                else {
                    int k0 = t * KT + 2 * p;
                    float v0 = (k0     < S1) ? vb[(size_t)k0 * HD + d]       : 0.f;
                    float v1 = (k0 + 1 < S1) ? vb[(size_t)(k0 + 1) * HD + d] : 0.f;
                    r = pack_f16x2(v0, v1);
                }
                vv[e] = r;
            }
            ((uint4*)vp)[(kt * 3 + j) * 32 + lane] = val;
        }
    }
}

// ================= flash attention v5: bf16 QK (24 mma) + f16 PV ============
__global__ void __launch_bounds__(256) k_flash5()
{
    __shared__ uint4 buf[2][768];           // per tile: K 384 uint4 | V 384 uint4

    const int tid = threadIdx.x, w = tid >> 5, lane = tid & 31;
    const int g = lane >> 2, tg = lane & 3;
    const int qt = blockIdx.x, bh = blockIdx.y;

    const float*    qb = g_q  + (size_t)bh * S1 * HD;
    const uint32_t* kp = g_kp + (size_t)bh * NTK * KP_TILE;
    const uint32_t* vp = g_vp + (size_t)bh * NTK * VP_TILE;

    // ---- Q fragments in bf16 (rows r0, r0+8), scaled ----
    const int r0 = qt * 128 + w * 16 + g;
    uint32_t qa[3][4];
    #pragma unroll
    for (int kt = 0; kt < 3; kt++) {
        int c0 = 16 * kt + 2 * tg;          // a0/a1 col base
        int c1 = c0 + 8;                    // a2/a3 col base
        float q00 = (c0     < HD) ? qb[(size_t)r0 * HD + c0] * 0.158113883f : 0.f;
        float q01 = (c0 + 1 < HD) ? qb[(size_t)r0 * HD + c0 + 1] * 0.158113883f : 0.f;
        float q10 = (c0     < HD) ? qb[(size_t)(r0 + 8) * HD + c0] * 0.158113883f : 0.f;
        float q11 = (c0 + 1 < HD) ? qb[(size_t)(r0 + 8) * HD + c0 + 1] * 0.158113883f : 0.f;
        float q20 = (c1     < HD) ? qb[(size_t)r0 * HD + c1] * 0.158113883f : 0.f;
        float q21 = (c1 + 1 < HD) ? qb[(size_t)r0 * HD + c1 + 1] * 0.158113883f : 0.f;
        float q30 = (c1     < HD) ? qb[(size_t)(r0 + 8) * HD + c1] * 0.158113883f : 0.f;
        float q31 = (c1 + 1 < HD) ? qb[(size_t)(r0 + 8) * HD + c1 + 1] * 0.158113883f : 0.f;
        qa[kt][0] = pack_bf16x2(q00, q01);
        qa[kt][1] = pack_bf16x2(q10, q11);
        qa[kt][2] = pack_bf16x2(q20, q21);
        qa[kt][3] = pack_bf16x2(q30, q31);
    }

    float o[6][4];
    #pragma unroll
    for (int b = 0; b < 6; b++)
        #pragma unroll
        for (int c = 0; c < 4; c++) o[b][c] = 0.f;
    float m[2] = { -1e30f, -1e30f };

    const uint32_t sb0 = smem_u32(&buf[0][0]);
    const uint32_t sb1 = smem_u32(&buf[1][0]);
    const char* kg0 = (const char*)kp;
    const char* vg0 = (const char*)vp;

    // prefetch tile 0 (768 uint4 / 256 threads = 3 each)
    #pragma unroll
    for (int i = 0; i < 3; i++) {
        int idx = tid + i * 256;
        if (idx < 384) CP_ASYNC16(sb0 + idx * 16, kg0 + (size_t)idx * 16);
        else           CP_ASYNC16(sb0 + idx * 16, vg0 + (size_t)(idx - 384) * 16);
    }
    CP_COMMIT();

    for (int t = 0; t < NTK; t++) {
        CP_WAIT0();
        __syncthreads();

        if (t + 1 < NTK) {
            uint32_t sd = ((t + 1) & 1) ? sb1 : sb0;
            const char* kg = kg0 + (size_t)(t + 1) * KP_TILE * 4;
            const char* vg = vg0 + (size_t)(t + 1) * VP_TILE * 4;
            #pragma unroll
            for (int i = 0; i < 3; i++) {
                int idx = tid + i * 256;
                if (idx < 384) CP_ASYNC16(sd + idx * 16, kg + (size_t)idx * 16);
                else           CP_ASYNC16(sd + idx * 16, vg + (size_t)(idx - 384) * 16);
            }
            CP_COMMIT();
        }

        const uint4* K4 = (const uint4*)((t & 1) ? &buf[1][0] : &buf[0][0]);
        const uint4* V4 = K4 + 384;

        // ---- S = Q K^T (bf16 mma, 3 kt x 8 nt = 24) ----
        float s[8][4];
        #pragma unroll
        for (int b = 0; b < 8; b++)
            #pragma unroll
            for (int c = 0; c < 4; c++) s[b][c] = 0.f;

        #pragma unroll
        for (int kt = 0; kt < 3; kt++) {
            uint4 f0 = K4[(kt * 4 + 0) * 32 + lane];
            uint4 f1 = K4[(kt * 4 + 1) * 32 + lane];
            uint4 f2 = K4[(kt * 4 + 2) * 32 + lane];
            uint4 f3 = K4[(kt * 4 + 3) * 32 + lane];
            uint32_t bb[8][2];
            bb[0][0] = f0.x; bb[0][1] = f0.y;
            bb[1][0] = f0.z; bb[1][1] = f0.w;
            bb[2][0] = f1.x; bb[2][1] = f1.y;
            bb[3][0] = f1.z; bb[3][1] = f1.w;
            bb[4][0] = f2.x; bb[4][1] = f2.y;
            bb[5][0] = f2.z; bb[5][1] = f2.w;
            bb[6][0] = f3.x; bb[6][1] = f3.y;
            bb[7][0] = f3.z; bb[7][1] = f3.w;
            #pragma unroll
            for (int nt = 0; nt < 8; nt++) mma_bf16(s[nt], qa[kt], bb[nt]);
        }

        // ---- mask invalid keys (last tile only) ----
        if (t == NTK - 1) {
            #pragma unroll
            for (int nt = 0; nt < 8; nt++) {
                int base = t * KT + 8 * nt + 2 * tg;
                if (base     >= S1) { s[nt][0] = s[nt][2] = -1e30f; }
                if (base + 1 >= S1) { s[nt][1] = s[nt][3] = -1e30f; }
            }
        }

        // ---- online softmax ----
        float corr[2], mL[2];
        #pragma unroll
        for (int r = 0; r < 2; r++) {
            float mx = -1e30f;
            #pragma unroll
            for (int nt = 0; nt < 8; nt++) {
                mx = fmaxf(mx, s[nt][2 * r]);
                mx = fmaxf(mx, s[nt][2 * r + 1]);
            }
            mx = fmaxf(mx, __shfl_xor_sync(0xFFFFFFFFu, mx, 1));
            mx = fmaxf(mx, __shfl_xor_sync(0xFFFFFFFFu, mx, 2));
            float mn = fmaxf(m[r], mx);
            corr[r] = __expf(m[r] - mn);
            m[r] = mn;
            mL[r] = mn * L2E;
        }

        #pragma unroll
        for (int nt = 0; nt < 6; nt++) {
            o[nt][0] *= corr[0];
            o[nt][1] *= corr[0];
            o[nt][2] *= corr[1];
            o[nt][3] *= corr[1];
        }

        uint32_t pf[8][2];
        #pragma unroll
        for (int nt = 0; nt < 8; nt++) {
            float f0 = __fmaf_rn(s[nt][0], L2E, -mL[0]);
            float f1 = __fmaf_rn(s[nt][1], L2E, -mL[0]);
            float f2 = __fmaf_rn(s[nt][2], L2E, -mL[1]);
            float f3 = __fmaf_rn(s[nt][3], L2E, -mL[1]);
            pf[nt][0] = pack_ex2_f16x2(f0, f1);
            pf[nt][1] = pack_ex2_f16x2(f2, f3);
        }

        // ---- O += P V (f16 mma) ----
        #pragma unroll
        for (int kt = 0; kt < 4; kt++) {
            uint4 b0 = V4[(kt * 3 + 0) * 32 + lane];
            uint4 b1 = V4[(kt * 3 + 1) * 32 + lane];
            uint4 b2 = V4[(kt * 3 + 2) * 32 + lane];
            uint32_t bb[6][2];
            bb[0][0] = b0.x; bb[0][1] = b0.y;
            bb[1][0] = b0.z; bb[1][1] = b0.w;
            bb[2][0] = b1.x; bb[2][1] = b1.y;
            bb[3][0] = b1.z; bb[3][1] = b1.w;
            bb[4][0] = b2.x; bb[4][1] = b2.y;
            bb[5][0] = b2.z; bb[5][1] = b2.w;
            uint32_t aa[4] = { pf[2 * kt][0], pf[2 * kt][1],
                               pf[2 * kt + 1][0], pf[2 * kt + 1][1] };
            #pragma unroll
            for (int nt = 0; nt < 6; nt++) mma_f16(o[nt], aa, bb[nt]);
        }
    }

    // ---- epilogue: l from ones-column, normalize, store ----
    {
        float l0 = __shfl_sync(0xFFFFFFFFu, o[5][0], lane & ~3);
        float l1 = __shfl_sync(0xFFFFFFFFu, o[5][2], lane & ~3);
        float inv0 = 1.f / l0, inv1 = 1.f / l1;
        float* ob0 = g_att + ((size_t)bh * S1 + r0) * HD;
        float* ob1 = g_att + ((size_t)bh * S1 + r0 + 8) * HD;
        #pragma unroll
        for (int nt = 0; nt < 5; nt++) {
            int d = 8 * nt + 2 * tg;
            *(float2*)(ob0 + d) = make_float2(o[nt][0] * inv0, o[nt][1] * inv0);
            *(float2*)(ob1 + d) = make_float2(o[nt][2] * inv1, o[nt][3] * inv1);
        }
    }
}

// ================= conv v2 (unchanged round-9 WIN) ==========================
#define CONV_SMEM ((16384 + 16384 + 4160 + 10496) * 4)
__global__ void __launch_bounds__(256) k_conv2(const float* __restrict__ x,
                       const float* __restrict__ w1, const float* __restrict__ b1,
                       const float* __restrict__ w2, const float* __restrict__ b2,
                       const float* __restrict__ pe)
{
    extern __shared__ float cs[];
    float* xs  = cs;
    float* w1s = cs + 16384;
    float* o1s = cs + 32768;
    float* w2T = cs + 36928;

    const int i = blockIdx.x, b = blockIdx.y;
    const int tid = threadIdx.x;

    const float4* x4 = (const float4*)x;
    #pragma unroll
    for (int q = 0; q < 16; q++) {
        int idx = tid + q * 256;
        int c0 = idx >> 6, r = idx & 63, ky = r >> 5, w4 = r & 31;
        ((float4*)xs)[c0 * 64 + ky * 32 + w4] =
            x4[(size_t)((b * 64 + c0) * 128 + (2 * i + ky)) * 32 + w4];
    }
    #pragma unroll
    for (int q = 0; q < 16; q++) {
        int idx = tid + q * 256;
        ((float4*)w1s)[idx] = ((const float4*)w1)[idx];
    }
    for (int idx = tid; idx < 10240; idx += 256) {
        int c2 = idx >> 6, c1 = idx & 63;
        w2T[c1 * 164 + c2] = w2[idx];
    }
    __syncthreads();

    {
        const int j0  = (tid & 15) * 4;
        const int c10 = (tid >> 4) * 4;
        float a1[4][4] = {};
        #pragma unroll 4
        for (int c0 = 0; c0 < 64; c0++) {
            float4 wv[4];
            #pragma unroll
            for (int cc = 0; cc < 4; cc++)
                wv[cc] = *(float4*)&w1s[(c10 + cc) * 256 + c0 * 4];
            #pragma unroll
            for (int jj = 0; jj < 4; jj++) {
                float2 x0 = *(float2*)&xs[c0 * 256 + 2 * (j0 + jj)];
                float2 x1 = *(float2*)&xs[c0 * 256 + 128 + 2 * (j0 + jj)];
                #pragma unroll
                for (int cc = 0; cc < 4; cc++)
                    a1[jj][cc] += x0.x * wv[cc].x + x0.y * wv[cc].y
                                + x1.x * wv[cc].z + x1.y * wv[cc].w;
            }
        }
        #pragma unroll
        for (int jj = 0; jj < 4; jj++)
            #pragma unroll
            for (int cc = 0; cc < 4; cc++)
                o1s[(j0 + jj) * 65 + c10 + cc] = b1[c10 + cc] + a1[jj][cc];
    }
    __syncthreads();

    {
        const int jj2 = tid & 31;
        const int c20 = (tid >> 5) * 20;
        float a2[2][20] = {};
        #pragma unroll 4
        for (int c1 = 0; c1 < 64; c1++) {
            float p0 = o1s[(2 * jj2) * 65 + c1];
            float p1 = o1s[(2 * jj2 + 1) * 65 + c1];
            #pragma unroll
            for (int q = 0; q < 5; q++) {
                float4 wv = *(float4*)&w2T[c1 * 164 + c20 + q * 4];
                a2[0][q * 4 + 0] += p0 * wv.x; a2[1][q * 4 + 0] += p1 * wv.x;
                a2[0][q * 4 + 1] += p0 * wv.y; a2[1][q * 4 + 1] += p1 * wv.y;
                a2[0][q * 4 + 2] += p0 * wv.z; a2[1][q * 4 + 2] += p1 * wv.z;
                a2[0][q * 4 + 3] += p0 * wv.w; a2[1][q * 4 + 3] += p1 * wv.w;
            }
        }
        #pragma unroll
        for (int row = 0; row < 2; row++) {
            int j = 2 * jj2 + row;
            int s = i * 64 + j;
            float pev = pe[s];
            #pragma unroll
            for (int cc = 0; cc < 20; cc++) {
                int c2 = c20 + cc;
                float v = a2[row][cc] + b2[c2];
                v = (v >= 0.f) ? v : 0.01f * v;
                g_f[((size_t)b * S1 + s) * DM + c2] = v + pev;
            }
        }
    }
}

__global__ void k_pad(const float* __restrict__ pe)
{
    int t = blockIdx.x * blockDim.x + threadIdx.x;
    if (t < BATCH * DM) {
        int b = t / DM, c = t % DM;
        g_f[((size_t)b * S1 + SMAX) * DM + c] = pe[SMAX];
    }
}

// ================= QKV v2 (unchanged round-9 WIN) ===========================
#define QKV_SMEM ((160 * 64 + 40 * 161) * 4)
__global__ void __launch_bounds__(512) k_qkv2(const float* __restrict__ wq,
                                              const float* __restrict__ wk,
                                              const float* __restrict__ wv)
{
    extern __shared__ float qs[];
    float* fsT = qs;
    float* wsT = qs + 160 * 64;

    const int NROWS = BATCH * S1;
    int row0 = blockIdx.x * 64;
    const float* w = (blockIdx.y == 0) ? wq : ((blockIdx.y == 1) ? wk : wv);
    float* outp = (blockIdx.y == 0) ? g_q : ((blockIdx.y == 1) ? g_k : g_v);
    int tid = threadIdx.x;

    for (int idx = tid; idx < 64 * DM; idx += 512) {
        int mm = idx / DM, c = idx % DM;
        int gr = row0 + mm;
        fsT[c * 64 + mm] = (gr < NROWS) ? g_f[(size_t)gr * DM + c] : 0.f;
    }

    const int m0 = (tid >> 5) * 4;
    const int n0 = (tid & 31) * 5;
    float acc[4][5] = {};

    for (int c4 = 0; c4 < 4; c4++) {
        __syncthreads();
        for (int idx = tid; idx < DM * 40; idx += 512) {
            int n = idx / 40, kk = idx % 40;
            wsT[kk * 161 + n] = w[n * DM + c4 * 40 + kk];
        }
        __syncthreads();
        #pragma unroll 4
        for (int kk = 0; kk < 40; kk++) {
            int k = c4 * 40 + kk;
            float4 fv = *(float4*)&fsT[k * 64 + m0];
            #pragma unroll
            for (int i = 0; i < 5; i++) {
                float wv_ = wsT[kk * 161 + n0 + i];
                acc[0][i] = __fmaf_rn(fv.x, wv_, acc[0][i]);
                acc[1][i] = __fmaf_rn(fv.y, wv_, acc[1][i]);
                acc[2][i] = __fmaf_rn(fv.z, wv_, acc[2][i]);
                acc[3][i] = __fmaf_rn(fv.w, wv_, acc[3][i]);
            }
        }
    }

    #pragma unroll
    for (int mi = 0; mi < 4; mi++) {
        int gr = row0 + m0 + mi;
        if (gr >= NROWS) continue;
        int b = gr / S1, s = gr % S1;
        #pragma unroll
        for (int i = 0; i < 5; i++) {
            int n = n0 + i;
            int h = n / HD, d = n % HD;
            outp[(((size_t)b * NH + h) * S1 + s) * HD + d] = acc[mi][i];
        }
    }
}

// ================= LN stats (unchanged) =====================================
__global__ void __launch_bounds__(256) k_stats2()
{
    int gw = blockIdx.x * 8 + (threadIdx.x >> 5);
    int lane = threadIdx.x & 31;
    int b = gw >> 12, s = gw & 4095;

    float sum = 0.f, sq = 0.f;
    #pragma unroll
    for (int j = 0; j < 5; j++) {
        int c = lane + 32 * j;
        int h = c / HD, d = c % HD;
        float v = g_att[(((size_t)b * NH + h) * S1 + s) * HD + d];
        sum += v; sq += v * v;
    }
    #pragma unroll
    for (int off = 16; off > 0; off >>= 1) {
        sum += __shfl_xor_sync(0xFFFFFFFFu, sum, off);
        sq  += __shfl_xor_sync(0xFFFFFFFFu, sq, off);
    }
    if (lane == 0) {
        float mean = sum * (1.f / DM);
        float var  = sq * (1.f / DM) - mean * mean;
        g_stats[2 * gw]     = mean;
        g_stats[2 * gw + 1] = rsqrtf(var + 1e-5f);
    }
}

// ================= LN + residual + upsample (unchanged) =====================
__global__ void k_out(const float* __restrict__ ln_w, const float* __restrict__ ln_b,
                      float* __restrict__ out)
{
    int tx = threadIdx.x, ty = threadIdx.y;
    int j = blockIdx.x * 32 + tx;
    int i = blockIdx.y;
    int bz = blockIdx.z;
    int b = bz / 20, cg = bz % 20;
    int c = cg * 8 + ty;
    int s = i * 64 + j;
    int h = c / HD, d = c % HD;
    float v = g_att[(((size_t)b * NH + h) * S1 + s) * HD + d];
    float mean = g_stats[2 * (b * SMAX + s)];
    float rstd = g_stats[2 * (b * SMAX + s) + 1];
    float ln = (v - mean) * rstd * ln_w[c] + ln_b[c];
    float ov = ln + v;
    size_t base = (((size_t)b * DM + c) * 128 + 2 * i) * 128 + 2 * j;
    float2 v2 = make_float2(ov, ov);
    *(float2*)(out + base)       = v2;
    *(float2*)(out + base + 128) = v2;
}

// ---------------- launch ----------------
extern "C" void kernel_launch(void* const* d_in, const int* in_sizes, int n_in,
                              void* d_out, int out_size)
{
    const float* x   = (const float*)d_in[0];
    const float* w1  = (const float*)d_in[1];
    const float* b1  = (const float*)d_in[2];
    const float* w2  = (const float*)d_in[3];
    const float* b2  = (const float*)d_in[4];
    const float* pe  = (const float*)d_in[5];
    const float* wq  = (const float*)d_in[6];
    const float* wk  = (const float*)d_in[7];
    const float* wv  = (const float*)d_in[8];
    const float* lnw = (const float*)d_in[9];
    const float* lnb = (const float*)d_in[10];
    float* out = (float*)d_out;

    static int attr_set = 0;
    if (!attr_set) {
        cudaFuncSetAttribute(k_conv2, cudaFuncAttributeMaxDynamicSharedMemorySize, CONV_SMEM);
        cudaFuncSetAttribute(k_qkv2,  cudaFuncAttributeMaxDynamicSharedMemorySize, QKV_SMEM);
        attr_set = 1;
    }

    k_conv2<<<dim3(64, BATCH), 256, CONV_SMEM>>>(x, w1, b1, w2, b2, pe);
    k_pad<<<1, BATCH * DM>>>(pe);
    k_qkv2<<<dim3((BATCH * S1 + 63) / 64, 3), 512, QKV_SMEM>>>(wq, wk, wv);
    k_prep<<<dim3(NTK, BATCH * NH), 128>>>();
    k_flash5<<<dim3(SMAX / 128, BATCH * NH), 256>>>();
    k_stats2<<<BATCH * SMAX / 8, 256>>>();
    k_out<<<dim3(2, 64, BATCH * 20), dim3(32, 8)>>>(lnw, lnb, out);
}